// round 1
// baseline (speedup 1.0000x reference)
#include <cuda_runtime.h>

// Shapes (fixed by the problem)
#define BB 64
#define NN 21
#define HH 128
#define WW 128
// Total elements = 64*21*128*128 = 22,020,096 (divisible by 4)

static constexpr int PART_BLOCKS = 1184;   // 148 SMs * 8
static constexpr int THREADS = 256;

__device__ float g_partials[PART_BLOCKS];

__device__ __forceinline__ float warp_sum(float v) {
    #pragma unroll
    for (int off = 16; off > 0; off >>= 1)
        v += __shfl_down_sync(0xFFFFFFFFu, v, off);
    return v;
}

__global__ void __launch_bounds__(THREADS) mse_partial_kernel(
    const float4* __restrict__ pred,
    const float4* __restrict__ gt,
    int n4)
{
    float acc = 0.0f;
    int stride = gridDim.x * blockDim.x;
    for (int i = blockIdx.x * blockDim.x + threadIdx.x; i < n4; i += stride) {
        float4 a = pred[i];
        float4 b = gt[i];
        float d0 = a.x - b.x;
        float d1 = a.y - b.y;
        float d2 = a.z - b.z;
        float d3 = a.w - b.w;
        acc = fmaf(d0, d0, acc);
        acc = fmaf(d1, d1, acc);
        acc = fmaf(d2, d2, acc);
        acc = fmaf(d3, d3, acc);
    }

    __shared__ float smem[THREADS / 32];
    float w = warp_sum(acc);
    int lane = threadIdx.x & 31;
    int wid  = threadIdx.x >> 5;
    if (lane == 0) smem[wid] = w;
    __syncthreads();
    if (wid == 0) {
        float v = (lane < THREADS / 32) ? smem[lane] : 0.0f;
        v = warp_sum(v);
        if (lane == 0) g_partials[blockIdx.x] = v;
    }
}

__global__ void __launch_bounds__(1024) finalize_kernel(
    const float* __restrict__ pred,
    const float* __restrict__ kp,   // (B, N, 2) -> [x, y]
    float* __restrict__ out)
{
    float mse_acc = 0.0f;
    float pck_acc = 0.0f;

    for (int i = threadIdx.x; i < PART_BLOCKS; i += blockDim.x)
        mse_acc += g_partials[i];

    // keypoint gather: i = b*N + n, 0..1343
    for (int i = threadIdx.x; i < BB * NN; i += blockDim.x) {
        float xf = kp[2 * i + 0];
        float yf = kp[2 * i + 1];
        int x = (int)fminf(fmaxf(xf, 0.0f), (float)(WW - 1));
        int y = (int)fminf(fmaxf(yf, 0.0f), (float)(HH - 1));
        float v = pred[((long long)i * HH + y) * WW + x];
        float e = 1.0f - v;
        pck_acc = fmaf(e, e, pck_acc);
    }

    __shared__ float s1[32];
    __shared__ float s2[32];
    int lane = threadIdx.x & 31;
    int wid  = threadIdx.x >> 5;

    float m = warp_sum(mse_acc);
    float p = warp_sum(pck_acc);
    if (lane == 0) { s1[wid] = m; s2[wid] = p; }
    __syncthreads();
    if (wid == 0) {
        float mm = (lane < 32) ? s1[lane] : 0.0f;
        float pp = (lane < 32) ? s2[lane] : 0.0f;
        mm = warp_sum(mm);
        pp = warp_sum(pp);
        if (lane == 0) {
            float mse = mm / (float)((long long)BB * NN * HH * WW);
            float pck = pp / (float)(BB * NN);
            out[0] = mse + pck;   // total (weights are 1.0)
            out[1] = mse;
            out[2] = pck;
        }
    }
}

extern "C" void kernel_launch(void* const* d_in, const int* in_sizes, int n_in,
                              void* d_out, int out_size)
{
    const float* pred = (const float*)d_in[0];
    const float* gt   = (const float*)d_in[1];
    const float* kp   = (const float*)d_in[2];
    float* out = (float*)d_out;

    int n4 = (BB * NN * HH * WW) / 4;   // 5,505,024

    mse_partial_kernel<<<PART_BLOCKS, THREADS>>>(
        (const float4*)pred, (const float4*)gt, n4);
    finalize_kernel<<<1, 1024>>>(pred, kp, out);
}

// round 2
// speedup vs baseline: 1.0693x; 1.0693x over previous
#include <cuda_runtime.h>

// Shapes (fixed by the problem)
#define BB 64
#define NN 21
#define HH 128
#define WW 128
// Total elements = 64*21*128*128 = 22,020,096 ; /4 = 5,505,024 float4

static constexpr int PART_BLOCKS = 1184;   // 148 SMs * 8
static constexpr int THREADS = 256;
static constexpr int NKP = BB * NN;        // 1344 keypoints

__device__ float g_mse_part[PART_BLOCKS];
__device__ float g_pck_part[PART_BLOCKS];
__device__ unsigned int g_done_ctr;        // zero-initialized at load; reset by last block

__device__ __forceinline__ float warp_sum(float v) {
    #pragma unroll
    for (int off = 16; off > 0; off >>= 1)
        v += __shfl_down_sync(0xFFFFFFFFu, v, off);
    return v;
}

__global__ void __launch_bounds__(THREADS) fused_loss_kernel(
    const float4* __restrict__ pred4,
    const float4* __restrict__ gt4,
    const float*  __restrict__ pred,   // scalar view for gathers
    const float*  __restrict__ kp,     // (B, N, 2) -> [x, y]
    float* __restrict__ out,
    int n4)
{
    const int tid_global = blockIdx.x * THREADS + threadIdx.x;
    const int stride = gridDim.x * THREADS;

    // ---- keypoint gather (overlapped with streaming; first NKP threads) ----
    float pck_acc = 0.0f;
    if (tid_global < NKP) {
        float xf = kp[2 * tid_global + 0];
        float yf = kp[2 * tid_global + 1];
        int x = (int)fminf(fmaxf(xf, 0.0f), (float)(WW - 1));
        int y = (int)fminf(fmaxf(yf, 0.0f), (float)(HH - 1));
        float v = pred[(tid_global * HH + y) * WW + x];
        float e = 1.0f - v;
        pck_acc = e * e;
    }

    // ---- streaming MSE with 2 independent accumulators for MLP ----
    float acc0 = 0.0f, acc1 = 0.0f;
    int i = tid_global;
    for (; i + stride < n4; i += 2 * stride) {
        float4 a0 = pred4[i];
        float4 b0 = gt4[i];
        float4 a1 = pred4[i + stride];
        float4 b1 = gt4[i + stride];
        float d;
        d = a0.x - b0.x; acc0 = fmaf(d, d, acc0);
        d = a0.y - b0.y; acc0 = fmaf(d, d, acc0);
        d = a0.z - b0.z; acc0 = fmaf(d, d, acc0);
        d = a0.w - b0.w; acc0 = fmaf(d, d, acc0);
        d = a1.x - b1.x; acc1 = fmaf(d, d, acc1);
        d = a1.y - b1.y; acc1 = fmaf(d, d, acc1);
        d = a1.z - b1.z; acc1 = fmaf(d, d, acc1);
        d = a1.w - b1.w; acc1 = fmaf(d, d, acc1);
    }
    if (i < n4) {
        float4 a = pred4[i];
        float4 b = gt4[i];
        float d;
        d = a.x - b.x; acc0 = fmaf(d, d, acc0);
        d = a.y - b.y; acc0 = fmaf(d, d, acc0);
        d = a.z - b.z; acc0 = fmaf(d, d, acc0);
        d = a.w - b.w; acc0 = fmaf(d, d, acc0);
    }
    float mse_acc = acc0 + acc1;

    // ---- block reduction of both accumulators ----
    __shared__ float s1[THREADS / 32];
    __shared__ float s2[THREADS / 32];
    int lane = threadIdx.x & 31;
    int wid  = threadIdx.x >> 5;
    float m = warp_sum(mse_acc);
    float p = warp_sum(pck_acc);
    if (lane == 0) { s1[wid] = m; s2[wid] = p; }
    __syncthreads();

    __shared__ bool s_is_last;
    if (wid == 0) {
        float mm = (lane < THREADS / 32) ? s1[lane] : 0.0f;
        float pp = (lane < THREADS / 32) ? s2[lane] : 0.0f;
        mm = warp_sum(mm);
        pp = warp_sum(pp);
        if (lane == 0) {
            g_mse_part[blockIdx.x] = mm;
            g_pck_part[blockIdx.x] = pp;
            __threadfence();
            unsigned int prev = atomicAdd(&g_done_ctr, 1u);
            s_is_last = (prev == (unsigned int)(gridDim.x - 1));
        }
    }
    __syncthreads();

    // ---- last block finalizes ----
    if (s_is_last) {
        float ma = 0.0f, pa = 0.0f;
        for (int j = threadIdx.x; j < PART_BLOCKS; j += THREADS) {
            ma += g_mse_part[j];
            pa += g_pck_part[j];
        }
        float mw = warp_sum(ma);
        float pw = warp_sum(pa);
        if (lane == 0) { s1[wid] = mw; s2[wid] = pw; }
        __syncthreads();
        if (wid == 0) {
            float mm = (lane < THREADS / 32) ? s1[lane] : 0.0f;
            float pp = (lane < THREADS / 32) ? s2[lane] : 0.0f;
            mm = warp_sum(mm);
            pp = warp_sum(pp);
            if (lane == 0) {
                float mse = mm / (float)((long long)BB * NN * HH * WW);
                float pck = pp / (float)NKP;
                out[0] = mse + pck;   // total (weights are 1.0)
                out[1] = mse;
                out[2] = pck;
                g_done_ctr = 0;       // reset for next graph replay
            }
        }
    }
}

extern "C" void kernel_launch(void* const* d_in, const int* in_sizes, int n_in,
                              void* d_out, int out_size)
{
    const float* pred = (const float*)d_in[0];
    const float* gt   = (const float*)d_in[1];
    const float* kp   = (const float*)d_in[2];
    float* out = (float*)d_out;

    int n4 = (BB * NN * HH * WW) / 4;   // 5,505,024

    fused_loss_kernel<<<PART_BLOCKS, THREADS>>>(
        (const float4*)pred, (const float4*)gt, pred, kp, out, n4);
}